// round 15
// baseline (speedup 1.0000x reference)
#include <cuda_runtime.h>
#include <cuda_fp16.h>
#include <cstdint>

// ---------------------------------------------------------------------------
// Problem constants
// ---------------------------------------------------------------------------
#define G_SL   9
#define N_PR   4096
#define D_ORI  2048
#define D_FEAT 512
#define NCLS   21
#define M_TOT  (G_SL * N_PR)          // 36864

#define OFF1 (N_PR * 4)
#define OFF2 (OFF1 + G_SL * N_PR * 4)
#define OFF3 (OFF2 + G_SL * N_PR * NCLS)

// ---------------------------------------------------------------------------
// Device scratch (no cudaMalloc allowed) — NOTE: no g_Ah anymore.
// ---------------------------------------------------------------------------
__device__ __half g_Bh[(size_t)D_ORI * D_FEAT];   // attention_feat fp16 [K][N]
__device__ __half g_Wh[(size_t)G_SL * D_ORI * 32];// packed branch weights fp16
__device__ float  g_alpha[(size_t)M_TOT * 4];     // alpha logits (atomic accum)
__device__ float  g_alphacls[(size_t)M_TOT];      // alpha_cls logits

// ---------------------------------------------------------------------------
// PTX helpers
// ---------------------------------------------------------------------------
__device__ __forceinline__ uint32_t smem_u32(const void* p) {
    uint32_t a;
    asm("{ .reg .u64 t; cvta.to.shared.u64 t, %1; cvt.u32.u64 %0, t; }"
        : "=r"(a) : "l"(p));
    return a;
}

#define CP_ASYNC16(dst, src) \
    asm volatile("cp.async.cg.shared.global [%0], [%1], 16;" :: "r"(dst), "l"(src) : "memory")
#define CP_COMMIT() asm volatile("cp.async.commit_group;" ::: "memory")

__device__ __forceinline__ void ldsm_x4(uint32_t* r, uint32_t addr) {
    asm volatile("ldmatrix.sync.aligned.m8n8.x4.shared.b16 {%0,%1,%2,%3}, [%4];"
        : "=r"(r[0]), "=r"(r[1]), "=r"(r[2]), "=r"(r[3]) : "r"(addr));
}
__device__ __forceinline__ void ldsm_x4t(uint32_t* r, uint32_t addr) {
    asm volatile("ldmatrix.sync.aligned.m8n8.x4.trans.shared.b16 {%0,%1,%2,%3}, [%4];"
        : "=r"(r[0]), "=r"(r[1]), "=r"(r[2]), "=r"(r[3]) : "r"(addr));
}

__device__ __forceinline__ void mma_f16(float* c, const uint32_t* a, const uint32_t* b) {
    asm volatile(
        "mma.sync.aligned.m16n8k16.row.col.f32.f16.f16.f32 "
        "{%0,%1,%2,%3}, {%4,%5,%6,%7}, {%8,%9}, {%0,%1,%2,%3};"
        : "+f"(c[0]), "+f"(c[1]), "+f"(c[2]), "+f"(c[3])
        : "r"(a[0]), "r"(a[1]), "r"(a[2]), "r"(a[3]),
          "r"(b[0]), "r"(b[1]));
}

__device__ __forceinline__ uint32_t pack_h2(float x, float y) {
    __half2 h = __floats2half2_rn(x, y);
    return *reinterpret_cast<uint32_t*>(&h);
}

// ---------------------------------------------------------------------------
// Conversion kernel (attention_feat only, 4 MB read / 2 MB write)
// ---------------------------------------------------------------------------
__global__ void convert_kernel(const float* __restrict__ src,
                               __half* __restrict__ dst, int n8)
{
    int i = blockIdx.x * blockDim.x + threadIdx.x;
    if (i >= n8) return;
    float4 v0 = reinterpret_cast<const float4*>(src)[2 * i];
    float4 v1 = reinterpret_cast<const float4*>(src)[2 * i + 1];
    uint4 o;
    o.x = pack_h2(v0.x, v0.y);
    o.y = pack_h2(v0.z, v0.w);
    o.z = pack_h2(v1.x, v1.y);
    o.w = pack_h2(v1.z, v1.w);
    reinterpret_cast<uint4*>(dst)[i] = o;
}

// ---------------------------------------------------------------------------
// Prep: pack branch weights [G][2048 k][32 n] fp16 (cols 0-3 bbox, 4-24 cls)
// ---------------------------------------------------------------------------
__global__ void pack_weights_kernel(const float* __restrict__ bbox_w,
                                    const float* __restrict__ cls_w)
{
    int idx = blockIdx.x * blockDim.x + threadIdx.x;   // over G*2048
    if (idx >= G_SL * D_ORI) return;
    const int g = idx / D_ORI;
    const int d = idx % D_ORI;
    __half w[32];
#pragma unroll
    for (int c = 0; c < 4; c++)
        w[c] = __float2half_rn(bbox_w[((size_t)g * D_ORI + d) * 4 + c]);
#pragma unroll
    for (int c = 0; c < 21; c++)
        w[4 + c] = __float2half_rn(cls_w[((size_t)g * D_ORI + d) * 21 + c]);
#pragma unroll
    for (int c = 25; c < 32; c++) w[c] = __half(0.f);
    uint4* dst = reinterpret_cast<uint4*>(g_Wh + (size_t)idx * 32);
    const uint4* srcv = reinterpret_cast<const uint4*>(w);
#pragma unroll
    for (int i = 0; i < 4; i++) dst[i] = srcv[i];
}

// ---------------------------------------------------------------------------
// Unified kernel: blocks [0, NBLK_GEMM) = GEMM+relu+alpha, rest = branch.
// A is staged as f32 via cp.async (ASYNC!), then converted smem->smem into a
// double-buffered f16 ldsm region. No global f16 copy of features exists.
// ---------------------------------------------------------------------------
#define BM 128
#define BN 128
#define BK 32
#define KITERS (D_ORI / BK)                  // 64
#define APAD_F 36                            // f32 pad (row = 144 B)
#define AF32_STGB (BM * APAD_F * 4)          // 18432 bytes
#define BPAD 136
#define B_STGB (BK * BPAD * 2)               // 8704 bytes
#define STGB (AF32_STGB + B_STGB)            // 27136 bytes
#define CVT_PAD 40                           // f16 pad for ldsm buffer
#define CVT_STGB (BM * CVT_PAD * 2)          // 10240 bytes
#define CVT_BASE (3 * STGB)                  // 81408
#define SMEM_TOTAL_UNI (CVT_BASE + 2 * CVT_STGB)   // 101888 bytes
#define NBLK_GEMM ((D_FEAT / BN) * (M_TOT / BM))   // 1152
// --- branch path ---
#define WPAD 40
#define W_STGB (BK * WPAD * 2)               // 2560 bytes
#define BR_STGB (AF32_STGB + W_STGB)         // 20992 bytes
#define BR_CVT_BASE (3 * BR_STGB)            // 62976  (+2*10240 = 83456 <= total)
#define NBLK_BR ((N_PR / 128) * G_SL)        // 288

__global__ __launch_bounds__(256, 2)
void fused_kernel(const float* __restrict__ features,     // [G,N,2048] f32
                  const float* __restrict__ alpha_w,      // [G, 512, 4]
                  const float* __restrict__ alpha_w_cls,  // [G, 512, 1]
                  const float* __restrict__ delta_rois,   // [G, N, 5]
                  float* __restrict__ dpo_out,             // out1 [G,N,4]
                  float* __restrict__ cls_out)             // out2 [G,N,21]
{
    extern __shared__ char smem[];
    const uint32_t sb = smem_u32(smem);
    const int tid  = threadIdx.x;
    const int wid  = tid >> 5;
    const int lane = tid & 31;
    const int r  = lane >> 2;
    const int cq = lane & 3;
    const int q  = lane >> 3;
    const int t  = lane & 7;

    // conversion geometry (shared by both paths): 16 f32 per thread
    const int cv_row = tid >> 1;
    const int cv_c0  = (tid & 1) * 16;

    if (blockIdx.x < NBLK_GEMM) {
        // ================= GEMM + relu + alpha path =================
        const int bx = blockIdx.x & 3;
        const int by = blockIdx.x >> 2;
        const int m0 = by * BM;
        const int n0 = bx * BN;
        const int g  = by >> 5;
        const int mbase = (wid & 3) * 32;
        const int nbase = (wid >> 2) * 64;

        const float* Abase = features + (size_t)m0 * D_ORI;

        float acc[2][8][4];
#pragma unroll
        for (int mt = 0; mt < 2; mt++)
#pragma unroll
            for (int nt = 0; nt < 8; nt++)
#pragma unroll
                for (int i = 0; i < 4; i++) acc[mt][nt][i] = 0.f;

        auto load_stage = [&](int kiter, int slot) {
            const int k0 = kiter * BK;
            const uint32_t sA = sb + slot * STGB;
            const uint32_t sB = sA + AF32_STGB;
            // A f32: 128 rows x 8 chunks (16B = 4 f32) = 1024 -> 4/thread
#pragma unroll
            for (int i = 0; i < 4; i++) {
                int c = tid + i * 256;
                int row = c >> 3, c16 = c & 7;
                CP_ASYNC16(sA + row * (APAD_F * 4) + c16 * 16,
                           Abase + (size_t)row * D_ORI + k0 + c16 * 4);
            }
            // B f16: 32 rows x 16 chunks = 512 -> 2/thread
#pragma unroll
            for (int i = 0; i < 2; i++) {
                int c = tid + i * 256;
                int krow = c >> 4, c16 = c & 15;
                CP_ASYNC16(sB + krow * (BPAD * 2) + c16 * 16,
                           g_Bh + (size_t)(k0 + krow) * D_FEAT + n0 + c16 * 8);
            }
            CP_COMMIT();
        };

        load_stage(0, 0);
        load_stage(1, 1);

        for (int k = 0; k < KITERS; k++) {
            const int slot = k % 3;
            const int cv   = k & 1;

            if (k < KITERS - 2) asm volatile("cp.async.wait_group 1;" ::: "memory");
            else                asm volatile("cp.async.wait_group 0;" ::: "memory");
            __syncthreads();

            // convert A f32 (stage) -> f16 (cvt buffer cv)
            {
                const float* src = reinterpret_cast<const float*>(
                    smem + slot * STGB) + cv_row * APAD_F + cv_c0;
                char* dst = smem + CVT_BASE + cv * CVT_STGB
                          + cv_row * (CVT_PAD * 2) + cv_c0 * 2;
                float4 v0 = *reinterpret_cast<const float4*>(src + 0);
                float4 v1 = *reinterpret_cast<const float4*>(src + 4);
                float4 v2 = *reinterpret_cast<const float4*>(src + 8);
                float4 v3 = *reinterpret_cast<const float4*>(src + 12);
                uint4 o;
                o.x = pack_h2(v0.x, v0.y);
                o.y = pack_h2(v0.z, v0.w);
                o.z = pack_h2(v1.x, v1.y);
                o.w = pack_h2(v1.z, v1.w);
                *reinterpret_cast<uint4*>(dst) = o;
                uint4 p;
                p.x = pack_h2(v2.x, v2.y);
                p.y = pack_h2(v2.z, v2.w);
                p.z = pack_h2(v3.x, v3.y);
                p.w = pack_h2(v3.z, v3.w);
                *reinterpret_cast<uint4*>(dst + 16) = p;
            }
            __syncthreads();

            if (k + 2 < KITERS) load_stage(k + 2, (k + 2) % 3);

            const uint32_t sAh = sb + CVT_BASE + cv * CVT_STGB;
            const uint32_t sB  = sb + slot * STGB + AF32_STGB;

#pragma unroll
            for (int kk = 0; kk < 2; kk++) {
                uint32_t af[2][4];
#pragma unroll
                for (int mt = 0; mt < 2; mt++) {
                    const int arow = mbase + mt * 16 + (q & 1) * 8 + t;
                    const int acol = kk * 16 + (q >> 1) * 8;
                    ldsm_x4(af[mt], sAh + (arow * CVT_PAD + acol) * 2);
                }
                uint32_t bf[4][4];
#pragma unroll
                for (int p = 0; p < 4; p++) {
                    const int krow = kk * 16 + (q & 1) * 8 + t;
                    const int ncol = nbase + p * 16 + (q >> 1) * 8;
                    ldsm_x4t(bf[p], sB + (krow * BPAD + ncol) * 2);
                }
#pragma unroll
                for (int mt = 0; mt < 2; mt++)
#pragma unroll
                    for (int nt = 0; nt < 8; nt++)
                        mma_f16(acc[mt][nt], af[mt], &bf[nt >> 1][(nt & 1) * 2]);
            }
        }

        // relu in registers
#pragma unroll
        for (int mt = 0; mt < 2; mt++)
#pragma unroll
            for (int nt = 0; nt < 8; nt++)
#pragma unroll
                for (int i = 0; i < 4; i++) acc[mt][nt][i] = fmaxf(acc[mt][nt][i], 0.f);

        // stage alpha weights for this CTA's 128 columns
        __syncthreads();
        float* wA = reinterpret_cast<float*>(smem);     // [128][6]
        if (tid < 128) {
            const int c = tid;
#pragma unroll
            for (int f = 0; f < 4; f++)
                wA[c * 6 + f] = alpha_w[((size_t)g * D_FEAT + n0 + c) * 4 + f];
            wA[c * 6 + 4] = alpha_w_cls[(size_t)g * D_FEAT + n0 + c];
        }
        __syncthreads();

        // alpha partials: per row dot over 16 owned cols, quad-reduce
#pragma unroll
        for (int mt = 0; mt < 2; mt++) {
#pragma unroll
            for (int h = 0; h < 2; h++) {
                float s[5] = {0.f, 0.f, 0.f, 0.f, 0.f};
#pragma unroll
                for (int nt = 0; nt < 8; nt++) {
                    const int col = nbase + nt * 8 + cq * 2;
                    const float v0 = acc[mt][nt][2 * h + 0];
                    const float v1 = acc[mt][nt][2 * h + 1];
#pragma unroll
                    for (int f = 0; f < 5; f++)
                        s[f] += v0 * wA[col * 6 + f] + v1 * wA[(col + 1) * 6 + f];
                }
#pragma unroll
                for (int f = 0; f < 5; f++) {
                    s[f] += __shfl_xor_sync(0xFFFFFFFF, s[f], 1);
                    s[f] += __shfl_xor_sync(0xFFFFFFFF, s[f], 2);
                }
                if (cq == 0) {
                    const int grow = m0 + mbase + mt * 16 + h * 8 + r;
#pragma unroll
                    for (int f = 0; f < 4; f++)
                        atomicAdd(&g_alpha[(size_t)grow * 4 + f], s[f]);
                    atomicAdd(&g_alphacls[grow], s[4]);
                }
            }
        }
    } else {
        // ================= branch GEMM path =================
        const int idx = blockIdx.x - NBLK_GEMM;
        const int g  = idx >> 5;
        const int n0 = (idx & 31) * 128;

        const float* Abase = features + ((size_t)g * N_PR + n0) * D_ORI;
        const __half* Wbase = g_Wh + (size_t)g * D_ORI * 32;

        float acc[4][4];
#pragma unroll
        for (int nt = 0; nt < 4; nt++)
#pragma unroll
            for (int i = 0; i < 4; i++) acc[nt][i] = 0.f;

        auto load_stage = [&](int kiter, int slot) {
            const int k0 = kiter * BK;
            const uint32_t sA = sb + slot * BR_STGB;
            const uint32_t sW = sA + AF32_STGB;
#pragma unroll
            for (int i = 0; i < 4; i++) {
                int c = tid + i * 256;
                int row = c >> 3, c16 = c & 7;
                CP_ASYNC16(sA + row * (APAD_F * 4) + c16 * 16,
                           Abase + (size_t)row * D_ORI + k0 + c16 * 4);
            }
            if (tid < 128) {
                int krow = tid >> 2, c16 = tid & 3;
                CP_ASYNC16(sW + krow * (WPAD * 2) + c16 * 16,
                           Wbase + (size_t)(k0 + krow) * 32 + c16 * 8);
            }
            CP_COMMIT();
        };

        load_stage(0, 0);
        load_stage(1, 1);

        for (int k = 0; k < KITERS; k++) {
            const int slot = k % 3;
            const int cv   = k & 1;

            if (k < KITERS - 2) asm volatile("cp.async.wait_group 1;" ::: "memory");
            else                asm volatile("cp.async.wait_group 0;" ::: "memory");
            __syncthreads();

            // convert A f32 (stage) -> f16 (cvt buffer cv)
            {
                const float* src = reinterpret_cast<const float*>(
                    smem + slot * BR_STGB) + cv_row * APAD_F + cv_c0;
                char* dst = smem + BR_CVT_BASE + cv * CVT_STGB
                          + cv_row * (CVT_PAD * 2) + cv_c0 * 2;
                float4 v0 = *reinterpret_cast<const float4*>(src + 0);
                float4 v1 = *reinterpret_cast<const float4*>(src + 4);
                float4 v2 = *reinterpret_cast<const float4*>(src + 8);
                float4 v3 = *reinterpret_cast<const float4*>(src + 12);
                uint4 o;
                o.x = pack_h2(v0.x, v0.y);
                o.y = pack_h2(v0.z, v0.w);
                o.z = pack_h2(v1.x, v1.y);
                o.w = pack_h2(v1.z, v1.w);
                *reinterpret_cast<uint4*>(dst) = o;
                uint4 p;
                p.x = pack_h2(v2.x, v2.y);
                p.y = pack_h2(v2.z, v2.w);
                p.z = pack_h2(v3.x, v3.y);
                p.w = pack_h2(v3.z, v3.w);
                *reinterpret_cast<uint4*>(dst + 16) = p;
            }
            __syncthreads();

            if (k + 2 < KITERS) load_stage(k + 2, (k + 2) % 3);

            const uint32_t sAh = sb + BR_CVT_BASE + cv * CVT_STGB;
            const uint32_t sW  = sb + slot * BR_STGB + AF32_STGB;

#pragma unroll
            for (int kk = 0; kk < 2; kk++) {
                uint32_t af[4];
                {
                    const int arow = wid * 16 + (q & 1) * 8 + t;
                    const int acol = kk * 16 + (q >> 1) * 8;
                    ldsm_x4(af, sAh + (arow * CVT_PAD + acol) * 2);
                }
                uint32_t bf[2][4];
#pragma unroll
                for (int p = 0; p < 2; p++) {
                    const int krow = kk * 16 + (q & 1) * 8 + t;
                    const int ncol = p * 16 + (q >> 1) * 8;
                    ldsm_x4t(bf[p], sW + (krow * WPAD + ncol) * 2);
                }
#pragma unroll
                for (int nt = 0; nt < 4; nt++)
                    mma_f16(acc[nt], af, &bf[nt >> 1][(nt & 1) * 2]);
            }
        }

        // epilogue: stage logits, per-row softmax/dpo
        __syncthreads();
        float* sT = reinterpret_cast<float*>(smem);     // [128][33]
        {
            const int r0 = wid * 16 + (lane >> 2);
#pragma unroll
            for (int nt = 0; nt < 4; nt++) {
                const int c0 = nt * 8 + cq * 2;
                sT[r0 * 33 + c0]           = acc[nt][0];
                sT[r0 * 33 + c0 + 1]       = acc[nt][1];
                sT[(r0 + 8) * 33 + c0]     = acc[nt][2];
                sT[(r0 + 8) * 33 + c0 + 1] = acc[nt][3];
            }
        }
        __syncthreads();

        if (tid < 128) {
            const int row = tid;
            const size_t gn = (size_t)g * N_PR + n0 + row;
            const float* L = sT + row * 33;

#pragma unroll
            for (int f = 0; f < 4; f++)
                dpo_out[gn * 4 + f] = delta_rois[gn * 5 + 1 + f] + L[f];

            float m = L[4];
#pragma unroll
            for (int c = 1; c < NCLS; c++) m = fmaxf(m, L[4 + c]);
            float e[NCLS], s = 0.f;
#pragma unroll
            for (int c = 0; c < NCLS; c++) {
                e[c] = expf(L[4 + c] - m);
                s += e[c];
            }
            const float inv = 1.f / s;
#pragma unroll
            for (int c = 0; c < NCLS; c++)
                cls_out[gn * NCLS + c] = e[c] * inv;
        }
    }
}

// ---------------------------------------------------------------------------
// Kernel C: softmax over G + final weighted sum
// ---------------------------------------------------------------------------
__global__ void finalize_kernel(const float* __restrict__ dpo,
                                float* __restrict__ out0,
                                float* __restrict__ out3)
{
    int n = blockIdx.x * blockDim.x + threadIdx.x;
    if (n >= N_PR) return;

#pragma unroll
    for (int f = 0; f < 4; f++) {
        float a[G_SL];
        float m = -1e30f;
#pragma unroll
        for (int g = 0; g < G_SL; g++) {
            a[g] = g_alpha[((size_t)g * N_PR + n) * 4 + f];
            m = fmaxf(m, a[g]);
        }
        float s = 0.f;
#pragma unroll
        for (int g = 0; g < G_SL; g++) {
            a[g] = expf(a[g] - m);
            s += a[g];
        }
        float inv = 1.f / s;
        float o = 0.f;
#pragma unroll
        for (int g = 0; g < G_SL; g++)
            o += dpo[((size_t)g * N_PR + n) * 4 + f] * a[g] * inv;
        out0[(size_t)n * 4 + f] = o;
    }

    {
        float a[G_SL];
        float m = -1e30f;
#pragma unroll
        for (int g = 0; g < G_SL; g++) {
            a[g] = g_alphacls[(size_t)g * N_PR + n];
            m = fmaxf(m, a[g]);
        }
        float s = 0.f;
#pragma unroll
        for (int g = 0; g < G_SL; g++) {
            a[g] = expf(a[g] - m);
            s += a[g];
        }
        float inv = 1.f / s;
#pragma unroll
        for (int g = 0; g < G_SL; g++)
            out3[(size_t)g * N_PR + n] = a[g] * inv;
    }
}

// ---------------------------------------------------------------------------
// Launch (single stream; no stream/event objects)
// ---------------------------------------------------------------------------
extern "C" void kernel_launch(void* const* d_in, const int* in_sizes, int n_in,
                              void* d_out, int out_size)
{
    const float* features     = (const float*)d_in[0];
    const float* delta_rois   = (const float*)d_in[3];
    const float* attention    = (const float*)d_in[5];
    const float* alpha_w      = (const float*)d_in[6];
    const float* bbox_regress = (const float*)d_in[7];
    const float* alpha_w_cls  = (const float*)d_in[8];
    const float* cls_w        = (const float*)d_in[9];

    float* out  = (float*)d_out;
    float* out0 = out;
    float* out1 = out + OFF1;
    float* out2 = out + OFF2;
    float* out3 = out + OFF3;

    static bool attr_set = false;
    if (!attr_set) {
        cudaFuncSetAttribute(fused_kernel,
                             cudaFuncAttributeMaxDynamicSharedMemorySize,
                             SMEM_TOTAL_UNI);
        attr_set = true;
    }

    // zero the atomic accumulators (graph-capturable)
    void* pA; cudaGetSymbolAddress(&pA, g_alpha);
    void* pC; cudaGetSymbolAddress(&pC, g_alphacls);
    cudaMemsetAsync(pA, 0, sizeof(float) * (size_t)M_TOT * 4, 0);
    cudaMemsetAsync(pC, 0, sizeof(float) * (size_t)M_TOT, 0);

    // convert attention_feat to fp16 (2 MB); pack branch weights
    void* pBh; cudaGetSymbolAddress(&pBh, g_Bh);
    {
        int b8 = (D_ORI * D_FEAT) / 8;
        convert_kernel<<<(b8 + 255) / 256, 256>>>(attention, (__half*)pBh, b8);
        pack_weights_kernel<<<(G_SL * D_ORI + 255) / 256, 256>>>(bbox_regress, cls_w);
    }

    // unified kernel: A staged as f32 (cp.async) + in-smem f16 conversion
    fused_kernel<<<NBLK_GEMM + NBLK_BR, 256, SMEM_TOTAL_UNI>>>(
        features, alpha_w, alpha_w_cls, delta_rois, out1, out2);

    // softmax over G + final output
    finalize_kernel<<<(N_PR + 255) / 256, 256>>>(out1, out0, out3);
}

// round 16
// speedup vs baseline: 1.1430x; 1.1430x over previous
#include <cuda_runtime.h>
#include <cuda_fp16.h>
#include <cstdint>

// ---------------------------------------------------------------------------
// Problem constants
// ---------------------------------------------------------------------------
#define G_SL   9
#define N_PR   4096
#define D_ORI  2048
#define D_FEAT 512
#define NCLS   21
#define M_TOT  (G_SL * N_PR)          // 36864

#define OFF1 (N_PR * 4)
#define OFF2 (OFF1 + G_SL * N_PR * 4)
#define OFF3 (OFF2 + G_SL * N_PR * NCLS)

// ---------------------------------------------------------------------------
// Device scratch (no cudaMalloc allowed)
// ---------------------------------------------------------------------------
__device__ __half g_Ah[(size_t)M_TOT * D_ORI];    // features fp16, written by phase 1
__device__ __half g_Bh[(size_t)D_ORI * D_FEAT];   // attention_feat fp16 [K][N]
__device__ __half g_Wh[(size_t)G_SL * D_ORI * 32];// packed branch weights fp16
__device__ float  g_alpha[(size_t)M_TOT * 4];     // alpha logits (atomic accum)
__device__ float  g_alphacls[(size_t)M_TOT];      // alpha_cls logits

// ---------------------------------------------------------------------------
// PTX helpers
// ---------------------------------------------------------------------------
__device__ __forceinline__ uint32_t smem_u32(const void* p) {
    uint32_t a;
    asm("{ .reg .u64 t; cvta.to.shared.u64 t, %1; cvt.u32.u64 %0, t; }"
        : "=r"(a) : "l"(p));
    return a;
}

#define CP_ASYNC16(dst, src) \
    asm volatile("cp.async.cg.shared.global [%0], [%1], 16;" :: "r"(dst), "l"(src) : "memory")
#define CP_COMMIT() asm volatile("cp.async.commit_group;" ::: "memory")

__device__ __forceinline__ void ldsm_x4(uint32_t* r, uint32_t addr) {
    asm volatile("ldmatrix.sync.aligned.m8n8.x4.shared.b16 {%0,%1,%2,%3}, [%4];"
        : "=r"(r[0]), "=r"(r[1]), "=r"(r[2]), "=r"(r[3]) : "r"(addr));
}
__device__ __forceinline__ void ldsm_x4t(uint32_t* r, uint32_t addr) {
    asm volatile("ldmatrix.sync.aligned.m8n8.x4.trans.shared.b16 {%0,%1,%2,%3}, [%4];"
        : "=r"(r[0]), "=r"(r[1]), "=r"(r[2]), "=r"(r[3]) : "r"(addr));
}

__device__ __forceinline__ void mma_f16(float* c, const uint32_t* a, const uint32_t* b) {
    asm volatile(
        "mma.sync.aligned.m16n8k16.row.col.f32.f16.f16.f32 "
        "{%0,%1,%2,%3}, {%4,%5,%6,%7}, {%8,%9}, {%0,%1,%2,%3};"
        : "+f"(c[0]), "+f"(c[1]), "+f"(c[2]), "+f"(c[3])
        : "r"(a[0]), "r"(a[1]), "r"(a[2]), "r"(a[3]),
          "r"(b[0]), "r"(b[1]));
}

__device__ __forceinline__ uint32_t pack_h2(float x, float y) {
    __half2 h = __floats2half2_rn(x, y);
    return *reinterpret_cast<uint32_t*>(&h);
}

// ---------------------------------------------------------------------------
// Conversion kernel (attention_feat only, 4 MB read / 2 MB write)
// ---------------------------------------------------------------------------
__global__ void convert_kernel(const float* __restrict__ src,
                               __half* __restrict__ dst, int n8)
{
    int i = blockIdx.x * blockDim.x + threadIdx.x;
    if (i >= n8) return;
    float4 v0 = reinterpret_cast<const float4*>(src)[2 * i];
    float4 v1 = reinterpret_cast<const float4*>(src)[2 * i + 1];
    uint4 o;
    o.x = pack_h2(v0.x, v0.y);
    o.y = pack_h2(v0.z, v0.w);
    o.z = pack_h2(v1.x, v1.y);
    o.w = pack_h2(v1.z, v1.w);
    reinterpret_cast<uint4*>(dst)[i] = o;
}

// ---------------------------------------------------------------------------
// Prep: pack branch weights [G][2048 k][32 n] fp16 (cols 0-3 bbox, 4-24 cls)
// ---------------------------------------------------------------------------
__global__ void pack_weights_kernel(const float* __restrict__ bbox_w,
                                    const float* __restrict__ cls_w)
{
    int idx = blockIdx.x * blockDim.x + threadIdx.x;   // over G*2048
    if (idx >= G_SL * D_ORI) return;
    const int g = idx / D_ORI;
    const int d = idx % D_ORI;
    __half w[32];
#pragma unroll
    for (int c = 0; c < 4; c++)
        w[c] = __float2half_rn(bbox_w[((size_t)g * D_ORI + d) * 4 + c]);
#pragma unroll
    for (int c = 0; c < 21; c++)
        w[4 + c] = __float2half_rn(cls_w[((size_t)g * D_ORI + d) * 21 + c]);
#pragma unroll
    for (int c = 25; c < 32; c++) w[c] = __half(0.f);
    uint4* dst = reinterpret_cast<uint4*>(g_Wh + (size_t)idx * 32);
    const uint4* srcv = reinterpret_cast<const uint4*>(w);
#pragma unroll
    for (int i = 0; i < 4; i++) dst[i] = srcv[i];
}

// ---------------------------------------------------------------------------
// PHASE 1: conv + branch GEMM. Per (g, 128-row tile):
//   - cp.async f32 A tiles (3-stage), convert smem->f16 (double buffer)
//   - STG converted f16 tile to g_Ah (the conversion pass lives here)
//   - ldsm+mma for offset(4)+cls(21); epilogue dpo + cls softmax.
// ---------------------------------------------------------------------------
#define BRK 32
#define BRKITERS (D_ORI / BRK)               // 64
#define APAD_F 36                            // f32 pad
#define AF32_STGB (128 * APAD_F * 4)         // 18432 bytes
#define WPAD 40
#define W_STGB (BRK * WPAD * 2)              // 2560 bytes
#define P1_STGB (AF32_STGB + W_STGB)         // 20992 bytes
#define CVT_PAD 40
#define CVT_STGB (128 * CVT_PAD * 2)         // 10240 bytes
#define P1_CVT_BASE (3 * P1_STGB)            // 62976
#define SMEM_P1 (P1_CVT_BASE + 2 * CVT_STGB) // 83456 bytes

__global__ __launch_bounds__(256, 2)
void conv_branch_kernel(const float* __restrict__ features,   // f32
                        const float* __restrict__ delta_rois, // [G,N,5]
                        float* __restrict__ dpo_out,           // out1
                        float* __restrict__ cls_out)           // out2
{
    extern __shared__ char smem[];
    const uint32_t sb = smem_u32(smem);
    const int tid  = threadIdx.x;
    const int wid  = tid >> 5;
    const int lane = tid & 31;
    const int cq = lane & 3;
    const int q  = lane >> 3;
    const int t  = lane & 7;

    const int g  = blockIdx.y;
    const int n0 = blockIdx.x * 128;

    const float*  Abase = features + ((size_t)g * N_PR + n0) * D_ORI;
    const __half* Wbase = g_Wh + (size_t)g * D_ORI * 32;
    __half* Aout = g_Ah + ((size_t)g * N_PR + n0) * D_ORI;

    const int cv_row = tid >> 1;
    const int cv_c0  = (tid & 1) * 16;

    float acc[4][4];
#pragma unroll
    for (int nt = 0; nt < 4; nt++)
#pragma unroll
        for (int i = 0; i < 4; i++) acc[nt][i] = 0.f;

    auto load_stage = [&](int kiter, int slot) {
        const int k0 = kiter * BRK;
        const uint32_t sA = sb + slot * P1_STGB;
        const uint32_t sW = sA + AF32_STGB;
        // A f32: 128 rows x 8 chunks (16B) = 1024 -> 4/thread
#pragma unroll
        for (int i = 0; i < 4; i++) {
            int c = tid + i * 256;
            int row = c >> 3, c16 = c & 7;
            CP_ASYNC16(sA + row * (APAD_F * 4) + c16 * 16,
                       Abase + (size_t)row * D_ORI + k0 + c16 * 4);
        }
        // W f16: 32 rows x 4 chunks = 128 -> tid<128
        if (tid < 128) {
            int krow = tid >> 2, c16 = tid & 3;
            CP_ASYNC16(sW + krow * (WPAD * 2) + c16 * 16,
                       Wbase + (size_t)(k0 + krow) * 32 + c16 * 8);
        }
        CP_COMMIT();
    };

    load_stage(0, 0);
    load_stage(1, 1);

    for (int k = 0; k < BRKITERS; k++) {
        const int slot = k % 3;
        const int cv   = k & 1;
        const int k0   = k * BRK;

        if (k < BRKITERS - 2) asm volatile("cp.async.wait_group 1;" ::: "memory");
        else                  asm volatile("cp.async.wait_group 0;" ::: "memory");
        __syncthreads();

        // convert f32 stage -> f16 cvt buffer + write-through to g_Ah
        {
            const float* src = reinterpret_cast<const float*>(
                smem + slot * P1_STGB) + cv_row * APAD_F + cv_c0;
            char* dst = smem + P1_CVT_BASE + cv * CVT_STGB
                      + cv_row * (CVT_PAD * 2) + cv_c0 * 2;
            float4 v0 = *reinterpret_cast<const float4*>(src + 0);
            float4 v1 = *reinterpret_cast<const float4*>(src + 4);
            float4 v2 = *reinterpret_cast<const float4*>(src + 8);
            float4 v3 = *reinterpret_cast<const float4*>(src + 12);
            uint4 o;
            o.x = pack_h2(v0.x, v0.y);
            o.y = pack_h2(v0.z, v0.w);
            o.z = pack_h2(v1.x, v1.y);
            o.w = pack_h2(v1.z, v1.w);
            uint4 p;
            p.x = pack_h2(v2.x, v2.y);
            p.y = pack_h2(v2.z, v2.w);
            p.z = pack_h2(v3.x, v3.y);
            p.w = pack_h2(v3.z, v3.w);
            *reinterpret_cast<uint4*>(dst) = o;
            *reinterpret_cast<uint4*>(dst + 16) = p;
            // write-through to global f16 copy
            uint4* gout = reinterpret_cast<uint4*>(
                Aout + (size_t)cv_row * D_ORI + k0 + cv_c0);
            gout[0] = o;
            gout[1] = p;
        }
        __syncthreads();

        if (k + 2 < BRKITERS) load_stage(k + 2, (k + 2) % 3);

        const uint32_t sAh = sb + P1_CVT_BASE + cv * CVT_STGB;
        const uint32_t sW  = sb + slot * P1_STGB + AF32_STGB;

#pragma unroll
        for (int kk = 0; kk < 2; kk++) {
            uint32_t af[4];
            {
                const int arow = wid * 16 + (q & 1) * 8 + t;
                const int acol = kk * 16 + (q >> 1) * 8;
                ldsm_x4(af, sAh + (arow * CVT_PAD + acol) * 2);
            }
            uint32_t bf[2][4];
#pragma unroll
            for (int p = 0; p < 2; p++) {
                const int krow = kk * 16 + (q & 1) * 8 + t;
                const int ncol = p * 16 + (q >> 1) * 8;
                ldsm_x4t(bf[p], sW + (krow * WPAD + ncol) * 2);
            }
#pragma unroll
            for (int nt = 0; nt < 4; nt++)
                mma_f16(acc[nt], af, &bf[nt >> 1][(nt & 1) * 2]);
        }
    }

    // ---- epilogue: stage logits, per-row softmax/dpo ----
    __syncthreads();
    float* sT = reinterpret_cast<float*>(smem);     // [128][33]
    {
        const int r0 = wid * 16 + (lane >> 2);
#pragma unroll
        for (int nt = 0; nt < 4; nt++) {
            const int c0 = nt * 8 + cq * 2;
            sT[r0 * 33 + c0]           = acc[nt][0];
            sT[r0 * 33 + c0 + 1]       = acc[nt][1];
            sT[(r0 + 8) * 33 + c0]     = acc[nt][2];
            sT[(r0 + 8) * 33 + c0 + 1] = acc[nt][3];
        }
    }
    __syncthreads();

    if (tid < 128) {
        const int row = tid;
        const size_t gn = (size_t)g * N_PR + n0 + row;
        const float* L = sT + row * 33;

#pragma unroll
        for (int f = 0; f < 4; f++)
            dpo_out[gn * 4 + f] = delta_rois[gn * 5 + 1 + f] + L[f];

        float m = L[4];
#pragma unroll
        for (int c = 1; c < NCLS; c++) m = fmaxf(m, L[4 + c]);
        float e[NCLS], s = 0.f;
#pragma unroll
        for (int c = 0; c < NCLS; c++) {
            e[c] = expf(L[4 + c] - m);
            s += e[c];
        }
        const float inv = 1.f / s;
#pragma unroll
        for (int c = 0; c < NCLS; c++)
            cls_out[gn * NCLS + c] = e[c] * inv;
    }
}

// ---------------------------------------------------------------------------
// PHASE 2: GEMM + relu + alpha (round-8 config verbatim; reads g_Ah f16).
//   CTA tile 128x128, BK=64, 3-stage cp.async, 256 threads, 2 CTAs/SM.
// ---------------------------------------------------------------------------
#define BM 128
#define BN 128
#define BK 64
#define APAD 72
#define BPAD 136
#define KITERS (D_ORI / BK)                  // 32
#define ASTGB (BM * APAD * 2)                // 18432 bytes
#define BSTGB (BK * BPAD * 2)                // 17408 bytes
#define STGB  (ASTGB + BSTGB)                // 35840 bytes
#define SMEM_GEMM_TOTAL (3 * STGB)           // 107520 bytes

__global__ __launch_bounds__(256, 2)
void gemm_alpha_kernel(const float* __restrict__ alpha_w,      // [G, 512, 4]
                       const float* __restrict__ alpha_w_cls)  // [G, 512, 1]
{
    extern __shared__ char smem[];
    const uint32_t sb = smem_u32(smem);
    const int tid  = threadIdx.x;
    const int wid  = tid >> 5;
    const int lane = tid & 31;
    const int r  = lane >> 2;
    const int cq = lane & 3;
    const int q  = lane >> 3;
    const int t  = lane & 7;

    const int m0 = blockIdx.y * BM;
    const int n0 = blockIdx.x * BN;
    const int g  = blockIdx.y >> 5;
    const int mbase = (wid & 3) * 32;
    const int nbase = (wid >> 2) * 64;

    const __half* Abase = g_Ah + (size_t)m0 * D_ORI;

    float acc[2][8][4];
#pragma unroll
    for (int mt = 0; mt < 2; mt++)
#pragma unroll
        for (int nt = 0; nt < 8; nt++)
#pragma unroll
            for (int i = 0; i < 4; i++) acc[mt][nt][i] = 0.f;

    auto load_stage = [&](int kiter, int slot) {
        const int k0 = kiter * BK;
        const uint32_t sA = sb + slot * STGB;
        const uint32_t sB = sA + ASTGB;
#pragma unroll
        for (int i = 0; i < 4; i++) {             // A: 1024 chunks
            int c = tid + i * 256;
            int row = c >> 3, c16 = c & 7;
            CP_ASYNC16(sA + row * (APAD * 2) + c16 * 16,
                       Abase + (size_t)row * D_ORI + k0 + c16 * 8);
        }
#pragma unroll
        for (int i = 0; i < 4; i++) {             // B: 1024 chunks
            int c = tid + i * 256;
            int krow = c >> 4, c16 = c & 15;
            CP_ASYNC16(sB + krow * (BPAD * 2) + c16 * 16,
                       g_Bh + (size_t)(k0 + krow) * D_FEAT + n0 + c16 * 8);
        }
        CP_COMMIT();
    };

    load_stage(0, 0);
    load_stage(1, 1);

    for (int k = 0; k < KITERS; k++) {
        const int slot = k % 3;

        if (k < KITERS - 2) asm volatile("cp.async.wait_group 1;" ::: "memory");
        else                asm volatile("cp.async.wait_group 0;" ::: "memory");
        __syncthreads();

        if (k + 2 < KITERS) load_stage(k + 2, (k + 2) % 3);

        const uint32_t sA = sb + slot * STGB;
        const uint32_t sB = sA + ASTGB;

#pragma unroll
        for (int kk = 0; kk < 4; kk++) {
            uint32_t af[2][4];
#pragma unroll
            for (int mt = 0; mt < 2; mt++) {
                const int arow = mbase + mt * 16 + (q & 1) * 8 + t;
                const int acol = kk * 16 + (q >> 1) * 8;
                ldsm_x4(af[mt], sA + (arow * APAD + acol) * 2);
            }
            uint32_t bf[4][4];
#pragma unroll
            for (int p = 0; p < 4; p++) {
                const int krow = kk * 16 + (q & 1) * 8 + t;
                const int ncol = nbase + p * 16 + (q >> 1) * 8;
                ldsm_x4t(bf[p], sB + (krow * BPAD + ncol) * 2);
            }
#pragma unroll
            for (int mt = 0; mt < 2; mt++)
#pragma unroll
                for (int nt = 0; nt < 8; nt++)
                    mma_f16(acc[mt][nt], af[mt], &bf[nt >> 1][(nt & 1) * 2]);
        }
    }

    // relu in registers
#pragma unroll
    for (int mt = 0; mt < 2; mt++)
#pragma unroll
        for (int nt = 0; nt < 8; nt++)
#pragma unroll
            for (int i = 0; i < 4; i++) acc[mt][nt][i] = fmaxf(acc[mt][nt][i], 0.f);

    // stage alpha weights for this CTA's 128 columns
    __syncthreads();
    float* wA = reinterpret_cast<float*>(smem);     // [128][6]
    if (tid < 128) {
        const int c = tid;
#pragma unroll
        for (int f = 0; f < 4; f++)
            wA[c * 6 + f] = alpha_w[((size_t)g * D_FEAT + n0 + c) * 4 + f];
        wA[c * 6 + 4] = alpha_w_cls[(size_t)g * D_FEAT + n0 + c];
    }
    __syncthreads();

    // alpha partials: per row dot over 16 owned cols, quad-reduce
#pragma unroll
    for (int mt = 0; mt < 2; mt++) {
#pragma unroll
        for (int h = 0; h < 2; h++) {
            float s[5] = {0.f, 0.f, 0.f, 0.f, 0.f};
#pragma unroll
            for (int nt = 0; nt < 8; nt++) {
                const int col = nbase + nt * 8 + cq * 2;
                const float v0 = acc[mt][nt][2 * h + 0];
                const float v1 = acc[mt][nt][2 * h + 1];
#pragma unroll
                for (int f = 0; f < 5; f++)
                    s[f] += v0 * wA[col * 6 + f] + v1 * wA[(col + 1) * 6 + f];
            }
#pragma unroll
            for (int f = 0; f < 5; f++) {
                s[f] += __shfl_xor_sync(0xFFFFFFFF, s[f], 1);
                s[f] += __shfl_xor_sync(0xFFFFFFFF, s[f], 2);
            }
            if (cq == 0) {
                const int grow = m0 + mbase + mt * 16 + h * 8 + r;
#pragma unroll
                for (int f = 0; f < 4; f++)
                    atomicAdd(&g_alpha[(size_t)grow * 4 + f], s[f]);
                atomicAdd(&g_alphacls[grow], s[4]);
            }
        }
    }
}

// ---------------------------------------------------------------------------
// Kernel C: softmax over G + final weighted sum
// ---------------------------------------------------------------------------
__global__ void finalize_kernel(const float* __restrict__ dpo,
                                float* __restrict__ out0,
                                float* __restrict__ out3)
{
    int n = blockIdx.x * blockDim.x + threadIdx.x;
    if (n >= N_PR) return;

#pragma unroll
    for (int f = 0; f < 4; f++) {
        float a[G_SL];
        float m = -1e30f;
#pragma unroll
        for (int g = 0; g < G_SL; g++) {
            a[g] = g_alpha[((size_t)g * N_PR + n) * 4 + f];
            m = fmaxf(m, a[g]);
        }
        float s = 0.f;
#pragma unroll
        for (int g = 0; g < G_SL; g++) {
            a[g] = expf(a[g] - m);
            s += a[g];
        }
        float inv = 1.f / s;
        float o = 0.f;
#pragma unroll
        for (int g = 0; g < G_SL; g++)
            o += dpo[((size_t)g * N_PR + n) * 4 + f] * a[g] * inv;
        out0[(size_t)n * 4 + f] = o;
    }

    {
        float a[G_SL];
        float m = -1e30f;
#pragma unroll
        for (int g = 0; g < G_SL; g++) {
            a[g] = g_alphacls[(size_t)g * N_PR + n];
            m = fmaxf(m, a[g]);
        }
        float s = 0.f;
#pragma unroll
        for (int g = 0; g < G_SL; g++) {
            a[g] = expf(a[g] - m);
            s += a[g];
        }
        float inv = 1.f / s;
#pragma unroll
        for (int g = 0; g < G_SL; g++)
            out3[(size_t)g * N_PR + n] = a[g] * inv;
    }
}

// ---------------------------------------------------------------------------
// Launch (single stream)
// ---------------------------------------------------------------------------
extern "C" void kernel_launch(void* const* d_in, const int* in_sizes, int n_in,
                              void* d_out, int out_size)
{
    const float* features     = (const float*)d_in[0];
    const float* delta_rois   = (const float*)d_in[3];
    const float* attention    = (const float*)d_in[5];
    const float* alpha_w      = (const float*)d_in[6];
    const float* bbox_regress = (const float*)d_in[7];
    const float* alpha_w_cls  = (const float*)d_in[8];
    const float* cls_w        = (const float*)d_in[9];

    float* out  = (float*)d_out;
    float* out0 = out;
    float* out1 = out + OFF1;
    float* out2 = out + OFF2;
    float* out3 = out + OFF3;

    static bool attr_set = false;
    if (!attr_set) {
        cudaFuncSetAttribute(conv_branch_kernel,
                             cudaFuncAttributeMaxDynamicSharedMemorySize,
                             SMEM_P1);
        cudaFuncSetAttribute(gemm_alpha_kernel,
                             cudaFuncAttributeMaxDynamicSharedMemorySize,
                             SMEM_GEMM_TOTAL);
        attr_set = true;
    }

    // zero the atomic accumulators (graph-capturable)
    void* pA; cudaGetSymbolAddress(&pA, g_alpha);
    void* pC; cudaGetSymbolAddress(&pC, g_alphacls);
    cudaMemsetAsync(pA, 0, sizeof(float) * (size_t)M_TOT * 4, 0);
    cudaMemsetAsync(pC, 0, sizeof(float) * (size_t)M_TOT, 0);

    // convert attention_feat to fp16 (2 MB); pack branch weights
    void* pBh; cudaGetSymbolAddress(&pBh, g_Bh);
    {
        int b8 = (D_ORI * D_FEAT) / 8;
        convert_kernel<<<(b8 + 255) / 256, 256>>>(attention, (__half*)pBh, b8);
        pack_weights_kernel<<<(G_SL * D_ORI + 255) / 256, 256>>>(bbox_regress, cls_w);
    }

    // PHASE 1: branch GEMM + feature conversion (writes g_Ah, out1, out2)
    conv_branch_kernel<<<dim3(N_PR / 128, G_SL), 256, SMEM_P1>>>(
        features, delta_rois, out1, out2);

    // PHASE 2: main GEMM + relu + alpha projection (reads g_Ah)
    gemm_alpha_kernel<<<dim3(D_FEAT / BN, M_TOT / BM), 256, SMEM_GEMM_TOTAL>>>(
        alpha_w, alpha_w_cls);

    // softmax over G + final output
    finalize_kernel<<<(N_PR + 255) / 256, 256>>>(out1, out0, out3);
}